// round 15
// baseline (speedup 1.0000x reference)
#include <cuda_runtime.h>

#define F_IN   512
#define H_DIM  16
#define C_OUT  7
#define NMAX   100000
#define EMAX   3200000
#define TOTMAX (NMAX + EMAX)
#define CHUNK  512
#define NCMAX  ((NMAX + CHUNK - 1) / CHUNK)

// -------- scratch (static device globals; no runtime allocation) --------
static __device__ float g_h0[NMAX * H_DIM];
static __device__ float g_h1[NMAX * H_DIM];
static __device__ int   g_counts[NMAX];
static __device__ int   g_cursor[NMAX];
static __device__ int   g_off[NMAX + 1];
static __device__ int   g_csr[TOTMAX];
static __device__ int   g_csums[NCMAX];

// packed f32x2 FMA: d = a*b + d (two fp32 lanes per instruction; PTX-only form)
__device__ __forceinline__ void fma2(unsigned long long& d,
                                     unsigned long long a, unsigned long long b)
{
    asm("fma.rn.f32x2 %0, %1, %2, %0;" : "+l"(d) : "l"(a), "l"(b));
}

__device__ __forceinline__ float unpack_sum(unsigned long long p)
{
    float lo = __uint_as_float((unsigned int)(p & 0xffffffffu));
    float hi = __uint_as_float((unsigned int)(p >> 32));
    return lo + hi;
}

// ======================= lin1: h = relu(x @ W1^T + b1) =======================
__global__ void k_lin1(const float* __restrict__ x, const float* __restrict__ W1,
                       const float* __restrict__ b1, float* __restrict__ h, int N)
{
    __shared__ float4 Ws[H_DIM * 129];
    const int tid = threadIdx.x;
    const float4* W14 = (const float4*)W1;
    for (int i = tid; i < H_DIM * 128; i += blockDim.x) {
        int k = i >> 7, j = i & 127;
        Ws[k * 129 + j] = W14[k * 128 + j];
    }
    __syncthreads();

    const int warp = tid >> 5, lane = tid & 31;
    const int k = lane & 15, slot = lane >> 4;
    const int row0 = (blockIdx.x * 8 + warp) * 8 + slot * 4;

    const int r0 = min(row0 + 0, N - 1);
    const int r1 = min(row0 + 1, N - 1);
    const int r2 = min(row0 + 2, N - 1);
    const int r3 = min(row0 + 3, N - 1);

    const float4* x4 = (const float4*)x;
    const float4* p0 = x4 + (size_t)r0 * 128;
    const float4* p1 = x4 + (size_t)r1 * 128;
    const float4* p2 = x4 + (size_t)r2 * 128;
    const float4* p3 = x4 + (size_t)r3 * 128;

    unsigned long long a0l = 0ull, a0h = 0ull, a1l = 0ull, a1h = 0ull;
    unsigned long long a2l = 0ull, a2h = 0ull, a3l = 0ull, a3h = 0ull;

    #pragma unroll 4
    for (int j = 0; j < 128; j++) {
        const float4 w = Ws[k * 129 + j];
        const ulonglong2 ww = *reinterpret_cast<const ulonglong2*>(&w);
        float4 v; ulonglong2 vv;
        v = p0[j]; vv = *reinterpret_cast<const ulonglong2*>(&v);
        fma2(a0l, vv.x, ww.x); fma2(a0h, vv.y, ww.y);
        v = p1[j]; vv = *reinterpret_cast<const ulonglong2*>(&v);
        fma2(a1l, vv.x, ww.x); fma2(a1h, vv.y, ww.y);
        v = p2[j]; vv = *reinterpret_cast<const ulonglong2*>(&v);
        fma2(a2l, vv.x, ww.x); fma2(a2h, vv.y, ww.y);
        v = p3[j]; vv = *reinterpret_cast<const ulonglong2*>(&v);
        fma2(a3l, vv.x, ww.x); fma2(a3h, vv.y, ww.y);
    }
    const float bk = b1[k];
    const float v0 = fmaxf(unpack_sum(a0l) + unpack_sum(a0h) + bk, 0.f);
    const float v1 = fmaxf(unpack_sum(a1l) + unpack_sum(a1h) + bk, 0.f);
    const float v2 = fmaxf(unpack_sum(a2l) + unpack_sum(a2h) + bk, 0.f);
    const float v3 = fmaxf(unpack_sum(a3l) + unpack_sum(a3h) + bk, 0.f);

    if (row0 + 0 < N) h[(row0 + 0) * H_DIM + k] = v0;
    if (row0 + 1 < N) h[(row0 + 1) * H_DIM + k] = v1;
    if (row0 + 2 < N) h[(row0 + 2) * H_DIM + k] = v2;
    if (row0 + 3 < N) h[(row0 + 3) * H_DIM + k] = v3;
}

// ======================= CSR build (dst-grouped, incl. self-loops) ===========
__global__ void k_count_init(int N)
{
    int i = blockIdx.x * blockDim.x + threadIdx.x;
    if (i < N) g_counts[i] = 1;   // self-loop
}

__global__ void k_count(const int* __restrict__ ei, int E)
{
    int t = blockIdx.x * blockDim.x + threadIdx.x;
    int e = t * 4;
    if (e + 3 < E) {
        int4 d = *(const int4*)(ei + E + e);
        atomicAdd(&g_counts[d.x], 1);
        atomicAdd(&g_counts[d.y], 1);
        atomicAdd(&g_counts[d.z], 1);
        atomicAdd(&g_counts[d.w], 1);
    } else {
        for (int j = e; j < E; j++) atomicAdd(&g_counts[ei[E + j]], 1);
    }
}

__global__ void k_csum(int N)
{
    const int c = blockIdx.x;
    const int tid = threadIdx.x;           // 256 threads
    const int i = c * CHUNK + tid;
    int s = 0;
    if (i < N) s = g_counts[i];
    if (i + 256 < N && tid + 256 < CHUNK) s += g_counts[i + 256];
    #pragma unroll
    for (int o = 16; o > 0; o >>= 1) s += __shfl_xor_sync(0xffffffffu, s, o);
    __shared__ int ws[8];
    if ((tid & 31) == 0) ws[tid >> 5] = s;
    __syncthreads();
    if (tid < 8) {
        int v = ws[tid];
        #pragma unroll
        for (int o = 4; o > 0; o >>= 1) v += __shfl_xor_sync(0x000000ffu, v, o);
        if (tid == 0) g_csums[c] = v;
    }
}

__global__ void k_scan(int NC)
{
    const int tid = threadIdx.x;           // 256 threads
    const int lane = tid & 31, w = tid >> 5;
    int v = (tid < NC) ? g_csums[tid] : 0;
    int x = v;
    #pragma unroll
    for (int o = 1; o < 32; o <<= 1) {
        int t = __shfl_up_sync(0xffffffffu, x, o);
        if (lane >= o) x += t;
    }
    __shared__ int wsum[8];
    if (lane == 31) wsum[w] = x;
    __syncthreads();
    if (tid < 8) {
        int y = wsum[tid];
        #pragma unroll
        for (int o = 1; o < 8; o <<= 1) {
            int t = __shfl_up_sync(0x000000ffu, y, o);
            if (tid >= o) y += t;
        }
        wsum[tid] = y;
    }
    __syncthreads();
    const int incl = x + (w ? wsum[w - 1] : 0);
    if (tid < NC) g_csums[tid] = incl - v;   // exclusive
}

__global__ void k_cscan(int N)
{
    const int c = blockIdx.x;
    const int tid = threadIdx.x;           // 512 threads
    const int i = c * CHUNK + tid;
    const int lane = tid & 31, w = tid >> 5;   // 16 warps
    const int v = (i < N) ? g_counts[i] : 0;
    int x = v;
    #pragma unroll
    for (int o = 1; o < 32; o <<= 1) {
        int t = __shfl_up_sync(0xffffffffu, x, o);
        if (lane >= o) x += t;
    }
    __shared__ int wsum[16];
    if (lane == 31) wsum[w] = x;
    __syncthreads();
    if (tid < 16) {
        int y = wsum[tid];
        #pragma unroll
        for (int o = 1; o < 16; o <<= 1) {
            int t = __shfl_up_sync(0x0000ffffu, y, o);
            if (tid >= o) y += t;
        }
        wsum[tid] = y;
    }
    __syncthreads();
    const int excl = x - v + (w ? wsum[w - 1] : 0);
    const int off = g_csums[c] + excl;
    if (i < N) {
        g_off[i] = off;
        g_cursor[i] = off;
        if (i == N - 1) g_off[N] = off + v;
    }
}

__global__ void k_scatter(const int* __restrict__ ei, int E, int N)
{
    int t = blockIdx.x * blockDim.x + threadIdx.x;
    if (t >= E + N) return;
    int s, d;
    if (t < E) { s = ei[t]; d = ei[E + t]; }
    else       { s = t - E; d = s; }
    int pos = atomicAdd(&g_cursor[d], 1);
    g_csr[pos] = s;
}

// ======================= fused AGNN layer (quad-coop, 1 wf/edge) =============
// L1tex-replay model: wavefronts = distinct 128B lines touched per LDG
// instruction. A 64B-aligned row lives in ONE 128B line, so 4 lanes loading
// the 4 quarters of the same src row in one LDG.128 = ONE wavefront/edge
// (was 2 with pair-coop). Layout: 8 lanes/node = 2 edge-slots x 4 lanes.
// Quad dot via shfl xor{1,2} (pd and ps are independent chains); norms on the
// fly; slot combine is a single xor-4 stage; stores fully coalesced. Not R6:
// two concurrent slots + N*8 threads keep edge parallelism. No softmax max
// (|logit| <= |beta|). Last layer fuses classify + log_softmax.
__global__ void k_agnn(const float* __restrict__ hin, float* __restrict__ hout,
                       const float* __restrict__ betap, int use_beta, int N,
                       int last, const float* __restrict__ W2,
                       const float* __restrict__ b2, float* __restrict__ out)
{
    const int gid = blockIdx.x * blockDim.x + threadIdx.x;
    int node = gid >> 3;
    const int o8   = gid & 7;        // position within octet
    const int q    = o8 & 3;         // 0..3  row quarter
    const int slot = o8 >> 2;        // 0..1  edge slot
    const unsigned quad_mask = 0xFu << ((threadIdx.x & 31) & ~3);
    const bool store_ok = (node < N);
    if (node >= N) node = N - 1;     // clamp: keep lanes alive for shuffles

    const float beta = use_beta ? betap[0] : 1.0f;
    const float4* __restrict__ h4 = (const float4*)hin;

    // this lane's quarter of the dst row + on-the-fly dst inverse norm
    const float4 hdv = h4[node * 4 + q];
    float sd = fmaf(hdv.x, hdv.x, fmaf(hdv.y, hdv.y,
               fmaf(hdv.z, hdv.z, hdv.w * hdv.w)));
    sd += __shfl_xor_sync(quad_mask, sd, 1);
    sd += __shfl_xor_sync(quad_mask, sd, 2);
    const float cd = beta * rsqrtf(fmaxf(sd, 1e-24f));

    const int beg = g_off[node], end = g_off[node + 1];

    float s = 0.f;
    float4 n = make_float4(0.f, 0.f, 0.f, 0.f);

    int i = beg + slot;
    if (i < end) {
        int src = g_csr[i];
        while (i < end) {
            const int csrc = src;
            const float4 a = h4[csrc * 4 + q];   // quad covers full row: 1 wf
            i += 2;
            if (i < end) src = g_csr[i];         // prefetch next edge's index
            float pd = fmaf(hdv.x, a.x, fmaf(hdv.y, a.y,
                       fmaf(hdv.z, a.z, hdv.w * a.w)));
            float ps = fmaf(a.x, a.x, fmaf(a.y, a.y,
                       fmaf(a.z, a.z, a.w * a.w)));
            pd += __shfl_xor_sync(quad_mask, pd, 1);
            ps += __shfl_xor_sync(quad_mask, ps, 1);
            pd += __shfl_xor_sync(quad_mask, pd, 2);
            ps += __shfl_xor_sync(quad_mask, ps, 2);
            const float w = __expf(cd * rsqrtf(fmaxf(ps, 1e-24f)) * pd);
            s += w;
            n.x = fmaf(w, a.x, n.x); n.y = fmaf(w, a.y, n.y);
            n.z = fmaf(w, a.z, n.z); n.w = fmaf(w, a.w, n.w);
        }
    }

    // combine the 2 slots (preserves quarter q); s becomes the full sum
    s   += __shfl_xor_sync(0xffffffffu, s, 4);
    n.x += __shfl_xor_sync(0xffffffffu, n.x, 4);
    n.y += __shfl_xor_sync(0xffffffffu, n.y, 4);
    n.z += __shfl_xor_sync(0xffffffffu, n.z, 4);
    n.w += __shfl_xor_sync(0xffffffffu, n.w, 4);

    if (slot == 0) {   // 4 lanes, each owns quarter q
        const float is = 1.0f / s;
        const float v0 = n.x * is, v1 = n.y * is, v2 = n.z * is, v3 = n.w * is;

        if (!last) {
            if (store_ok)
                ((float4*)hout)[node * 4 + q] = make_float4(v0, v1, v2, v3);
        } else {
            // fused classify + log_softmax: partial logits over this quarter
            float lg[C_OUT];
            #pragma unroll
            for (int c = 0; c < C_OUT; c++) {
                const float* wr = W2 + c * H_DIM + q * 4;
                lg[c] = fmaf(v0, wr[0], fmaf(v1, wr[1],
                        fmaf(v2, wr[2], v3 * wr[3])));
            }
            #pragma unroll
            for (int c = 0; c < C_OUT; c++) {
                lg[c] += __shfl_xor_sync(quad_mask, lg[c], 1);
                lg[c] += __shfl_xor_sync(quad_mask, lg[c], 2);
            }
            if (q == 0 && store_ok) {
                #pragma unroll
                for (int c = 0; c < C_OUT; c++) lg[c] += b2[c];
                float mx = lg[0];
                #pragma unroll
                for (int c = 1; c < C_OUT; c++) mx = fmaxf(mx, lg[c]);
                float ssum = 0.f;
                #pragma unroll
                for (int c = 0; c < C_OUT; c++) ssum += __expf(lg[c] - mx);
                const float lse = mx + __logf(ssum);
                #pragma unroll
                for (int c = 0; c < C_OUT; c++) out[node * C_OUT + c] = lg[c] - lse;
            }
        }
    }
}

// ======================= launch ==============================================
extern "C" void kernel_launch(void* const* d_in, const int* in_sizes, int n_in,
                              void* d_out, int out_size)
{
    const float* x     = (const float*)d_in[0];
    const int*   ei    = (const int*)d_in[1];
    const float* W1    = (const float*)d_in[2];
    const float* b1    = (const float*)d_in[3];
    const float* beta2 = (const float*)d_in[4];
    const float* beta3 = (const float*)d_in[5];
    const float* beta4 = (const float*)d_in[6];
    const float* W2    = (const float*)d_in[7];
    const float* b2    = (const float*)d_in[8];
    float* out = (float*)d_out;

    const int N = in_sizes[0] / F_IN;
    const int E = in_sizes[1] / 2;
    const int NC = (N + CHUNK - 1) / CHUNK;

    float *hA, *hB;
    cudaGetSymbolAddress((void**)&hA, g_h0);
    cudaGetSymbolAddress((void**)&hB, g_h1);

    // lin1
    k_lin1<<<(N + 63) / 64, 256>>>(x, W1, b1, hA, N);

    // CSR build
    k_count_init<<<(N + 255) / 256, 256>>>(N);
    k_count<<<((E + 3) / 4 + 255) / 256, 256>>>(ei, E);
    k_csum<<<NC, 256>>>(N);
    k_scan<<<1, 256>>>(NC);
    k_cscan<<<NC, 512>>>(N);
    k_scatter<<<(E + N + 255) / 256, 256>>>(ei, E, N);

    // 4 AGNN layers (layer 0: beta fixed at 1.0; layer 3 fuses classify)
    const float* betas[4] = {nullptr, beta2, beta3, beta4};
    float* cur = hA; float* nxt = hB;
    for (int l = 0; l < 4; l++) {
        const int last = (l == 3);
        k_agnn<<<(N * 8 + 255) / 256, 256>>>(cur, nxt,
                                             betas[l], l > 0 ? 1 : 0, N,
                                             last, W2, b2, out);
        float* t = cur; cur = nxt; nxt = t;
    }
}

// round 16
// speedup vs baseline: 1.0318x; 1.0318x over previous
#include <cuda_runtime.h>

#define F_IN   512
#define H_DIM  16
#define C_OUT  7
#define NMAX   100000
#define EMAX   3200000
#define CHUNK  512
#define NCMAX  ((NMAX + CHUNK - 1) / CHUNK)

// -------- scratch (static device globals; no runtime allocation) --------
static __device__ float g_h0[NMAX * H_DIM];
static __device__ float g_h1[NMAX * H_DIM];
static __device__ int   g_counts[NMAX];
static __device__ int   g_cursor[NMAX];
static __device__ int   g_off[NMAX + 1];
static __device__ int   g_csr[EMAX];
static __device__ int   g_csums[NCMAX];

// packed f32x2 FMA: d = a*b + d (two fp32 lanes per instruction; PTX-only form)
__device__ __forceinline__ void fma2(unsigned long long& d,
                                     unsigned long long a, unsigned long long b)
{
    asm("fma.rn.f32x2 %0, %1, %2, %0;" : "+l"(d) : "l"(a), "l"(b));
}

__device__ __forceinline__ float unpack_sum(unsigned long long p)
{
    float lo = __uint_as_float((unsigned int)(p & 0xffffffffu));
    float hi = __uint_as_float((unsigned int)(p >> 32));
    return lo + hi;
}

// ======================= lin1: h = relu(x @ W1^T + b1) =======================
__global__ void k_lin1(const float* __restrict__ x, const float* __restrict__ W1,
                       const float* __restrict__ b1, float* __restrict__ h, int N)
{
    __shared__ float4 Ws[H_DIM * 129];
    const int tid = threadIdx.x;
    const float4* W14 = (const float4*)W1;
    for (int i = tid; i < H_DIM * 128; i += blockDim.x) {
        int k = i >> 7, j = i & 127;
        Ws[k * 129 + j] = W14[k * 128 + j];
    }
    __syncthreads();

    const int warp = tid >> 5, lane = tid & 31;
    const int k = lane & 15, slot = lane >> 4;
    const int row0 = (blockIdx.x * 8 + warp) * 8 + slot * 4;

    const int r0 = min(row0 + 0, N - 1);
    const int r1 = min(row0 + 1, N - 1);
    const int r2 = min(row0 + 2, N - 1);
    const int r3 = min(row0 + 3, N - 1);

    const float4* x4 = (const float4*)x;
    const float4* p0 = x4 + (size_t)r0 * 128;
    const float4* p1 = x4 + (size_t)r1 * 128;
    const float4* p2 = x4 + (size_t)r2 * 128;
    const float4* p3 = x4 + (size_t)r3 * 128;

    unsigned long long a0l = 0ull, a0h = 0ull, a1l = 0ull, a1h = 0ull;
    unsigned long long a2l = 0ull, a2h = 0ull, a3l = 0ull, a3h = 0ull;

    #pragma unroll 4
    for (int j = 0; j < 128; j++) {
        const float4 w = Ws[k * 129 + j];
        const ulonglong2 ww = *reinterpret_cast<const ulonglong2*>(&w);
        float4 v; ulonglong2 vv;
        v = p0[j]; vv = *reinterpret_cast<const ulonglong2*>(&v);
        fma2(a0l, vv.x, ww.x); fma2(a0h, vv.y, ww.y);
        v = p1[j]; vv = *reinterpret_cast<const ulonglong2*>(&v);
        fma2(a1l, vv.x, ww.x); fma2(a1h, vv.y, ww.y);
        v = p2[j]; vv = *reinterpret_cast<const ulonglong2*>(&v);
        fma2(a2l, vv.x, ww.x); fma2(a2h, vv.y, ww.y);
        v = p3[j]; vv = *reinterpret_cast<const ulonglong2*>(&v);
        fma2(a3l, vv.x, ww.x); fma2(a3h, vv.y, ww.y);
    }
    const float bk = b1[k];
    const float v0 = fmaxf(unpack_sum(a0l) + unpack_sum(a0h) + bk, 0.f);
    const float v1 = fmaxf(unpack_sum(a1l) + unpack_sum(a1h) + bk, 0.f);
    const float v2 = fmaxf(unpack_sum(a2l) + unpack_sum(a2h) + bk, 0.f);
    const float v3 = fmaxf(unpack_sum(a3l) + unpack_sum(a3h) + bk, 0.f);

    if (row0 + 0 < N) h[(row0 + 0) * H_DIM + k] = v0;
    if (row0 + 1 < N) h[(row0 + 1) * H_DIM + k] = v1;
    if (row0 + 2 < N) h[(row0 + 2) * H_DIM + k] = v2;
    if (row0 + 3 < N) h[(row0 + 3) * H_DIM + k] = v3;
}

// ======================= CSR build (dst-grouped, REAL edges only) ============
// Self-loops are handled analytically inside k_agnn (cos(i,i)=1 exactly), so
// counts/csr cover only the E input edges; counts zeroed via cudaMemsetAsync.
__global__ void k_count(const int* __restrict__ ei, int E)
{
    int t = blockIdx.x * blockDim.x + threadIdx.x;
    int e = t * 4;
    if (e + 3 < E) {
        int4 d = *(const int4*)(ei + E + e);
        atomicAdd(&g_counts[d.x], 1);
        atomicAdd(&g_counts[d.y], 1);
        atomicAdd(&g_counts[d.z], 1);
        atomicAdd(&g_counts[d.w], 1);
    } else {
        for (int j = e; j < E; j++) atomicAdd(&g_counts[ei[E + j]], 1);
    }
}

__global__ void k_csum(int N)
{
    const int c = blockIdx.x;
    const int tid = threadIdx.x;           // 256 threads
    const int i = c * CHUNK + tid;
    int s = 0;
    if (i < N) s = g_counts[i];
    if (i + 256 < N && tid + 256 < CHUNK) s += g_counts[i + 256];
    #pragma unroll
    for (int o = 16; o > 0; o >>= 1) s += __shfl_xor_sync(0xffffffffu, s, o);
    __shared__ int ws[8];
    if ((tid & 31) == 0) ws[tid >> 5] = s;
    __syncthreads();
    if (tid < 8) {
        int v = ws[tid];
        #pragma unroll
        for (int o = 4; o > 0; o >>= 1) v += __shfl_xor_sync(0x000000ffu, v, o);
        if (tid == 0) g_csums[c] = v;
    }
}

__global__ void k_scan(int NC)
{
    const int tid = threadIdx.x;           // 256 threads
    const int lane = tid & 31, w = tid >> 5;
    int v = (tid < NC) ? g_csums[tid] : 0;
    int x = v;
    #pragma unroll
    for (int o = 1; o < 32; o <<= 1) {
        int t = __shfl_up_sync(0xffffffffu, x, o);
        if (lane >= o) x += t;
    }
    __shared__ int wsum[8];
    if (lane == 31) wsum[w] = x;
    __syncthreads();
    if (tid < 8) {
        int y = wsum[tid];
        #pragma unroll
        for (int o = 1; o < 8; o <<= 1) {
            int t = __shfl_up_sync(0x000000ffu, y, o);
            if (tid >= o) y += t;
        }
        wsum[tid] = y;
    }
    __syncthreads();
    const int incl = x + (w ? wsum[w - 1] : 0);
    if (tid < NC) g_csums[tid] = incl - v;   // exclusive
}

__global__ void k_cscan(int N)
{
    const int c = blockIdx.x;
    const int tid = threadIdx.x;           // 512 threads
    const int i = c * CHUNK + tid;
    const int lane = tid & 31, w = tid >> 5;   // 16 warps
    const int v = (i < N) ? g_counts[i] : 0;
    int x = v;
    #pragma unroll
    for (int o = 1; o < 32; o <<= 1) {
        int t = __shfl_up_sync(0xffffffffu, x, o);
        if (lane >= o) x += t;
    }
    __shared__ int wsum[16];
    if (lane == 31) wsum[w] = x;
    __syncthreads();
    if (tid < 16) {
        int y = wsum[tid];
        #pragma unroll
        for (int o = 1; o < 16; o <<= 1) {
            int t = __shfl_up_sync(0x0000ffffu, y, o);
            if (tid >= o) y += t;
        }
        wsum[tid] = y;
    }
    __syncthreads();
    const int excl = x - v + (w ? wsum[w - 1] : 0);
    const int off = g_csums[c] + excl;
    if (i < N) {
        g_off[i] = off;
        g_cursor[i] = off;
        if (i == N - 1) g_off[N] = off + v;
    }
}

__global__ void k_scatter(const int* __restrict__ ei, int E)
{
    int t = blockIdx.x * blockDim.x + threadIdx.x;
    if (t >= E) return;
    const int s = ei[t];
    const int d = ei[E + t];
    int pos = atomicAdd(&g_cursor[d], 1);
    g_csr[pos] = s;
}

// ======================= fused AGNN layer (pair-coop, 8 slots, self inline) ==
// R14 shape confirmed best for gather (pair = 2 lanes/edge; quad regressed:
// same bytes, more shuffles). Changes vs R14:
//  * 16 lanes/node = 8 edge-slots x 2 lanes -> warp covers 2 nodes (was 4):
//    intra-warp degree-imbalance drops ~2x; per-slot chains halve; per-edge
//    costs identical. Combine = xor{2,4,8}.
//  * self-loop handled analytically: w_self = exp(beta) (cos=1 exact), row
//    already in registers -> one less gathered edge per node; CSR holds only
//    real edges; degree-0 nodes fall out naturally.
// No softmax max (|logit| <= |beta|). Last layer fuses classify+log_softmax.
__global__ void k_agnn(const float* __restrict__ hin, float* __restrict__ hout,
                       const float* __restrict__ betap, int use_beta, int N,
                       int last, const float* __restrict__ W2,
                       const float* __restrict__ b2, float* __restrict__ out)
{
    const int gid = blockIdx.x * blockDim.x + threadIdx.x;
    int node = gid >> 4;
    const int o16  = gid & 15;       // position within the node's 16 lanes
    const int slot = o16 >> 1;       // 0..7  edge slot
    const int p    = o16 & 1;        // 0..1  row half
    const unsigned pair_mask = 3u << ((threadIdx.x & 31) & ~1);
    const bool store_ok = (node < N);
    if (node >= N) node = N - 1;     // clamp: keep lanes alive for shuffles

    const float beta = use_beta ? betap[0] : 1.0f;
    const float4* __restrict__ h4 = (const float4*)hin;

    // this lane's half of the dst row + on-the-fly dst inverse norm
    float hd[8];
    {
        float4 a = h4[node * 4 + p * 2 + 0];
        float4 b = h4[node * 4 + p * 2 + 1];
        hd[0] = a.x; hd[1] = a.y; hd[2] = a.z; hd[3] = a.w;
        hd[4] = b.x; hd[5] = b.y; hd[6] = b.z; hd[7] = b.w;
    }
    float sd = 0.f;
    #pragma unroll
    for (int q = 0; q < 8; q++) sd = fmaf(hd[q], hd[q], sd);
    sd += __shfl_xor_sync(pair_mask, sd, 1);
    const float cd = beta * rsqrtf(fmaxf(sd, 1e-24f));

    const int beg = g_off[node], end = g_off[node + 1];

    float s = 0.f;
    float n[8];
    #pragma unroll
    for (int q = 0; q < 8; q++) n[q] = 0.f;

    int i = beg + slot;
    if (i < end) {
        int src = g_csr[i];
        while (i < end) {
            const int csrc = src;
            const float4 a0 = h4[csrc * 4 + p * 2 + 0];
            const float4 a1 = h4[csrc * 4 + p * 2 + 1];
            i += 8;
            if (i < end) src = g_csr[i];   // prefetch next edge's index
            float hs[8];
            hs[0] = a0.x; hs[1] = a0.y; hs[2] = a0.z; hs[3] = a0.w;
            hs[4] = a1.x; hs[5] = a1.y; hs[6] = a1.z; hs[7] = a1.w;
            float pd = 0.f, ps = 0.f;
            #pragma unroll
            for (int q = 0; q < 8; q++) {
                pd = fmaf(hd[q], hs[q], pd);
                ps = fmaf(hs[q], hs[q], ps);
            }
            pd += __shfl_xor_sync(pair_mask, pd, 1);
            ps += __shfl_xor_sync(pair_mask, ps, 1);
            const float w = __expf(cd * rsqrtf(fmaxf(ps, 1e-24f)) * pd);
            s += w;
            #pragma unroll
            for (int q = 0; q < 8; q++) n[q] = fmaf(w, hs[q], n[q]);
        }
    }

    // combine across the 8 slots (preserves half p); s becomes the full sum
    #pragma unroll
    for (int o = 2; o <= 8; o <<= 1) {
        s += __shfl_xor_sync(0xffffffffu, s, o);
        #pragma unroll
        for (int q = 0; q < 8; q++)
            n[q] += __shfl_xor_sync(0xffffffffu, n[q], o);
    }

    if (slot == 0) {   // lanes o16==0 (half 0) and o16==1 (half 1)
        // analytic self-loop: cos(i,i) = 1 -> weight exp(beta); row in regs
        const float wself = __expf(beta);
        s += wself;
        #pragma unroll
        for (int q = 0; q < 8; q++) n[q] = fmaf(wself, hd[q], n[q]);

        const float is = 1.0f / s;
        float v[8];
        #pragma unroll
        for (int q = 0; q < 8; q++) v[q] = n[q] * is;

        if (!last) {
            if (store_ok) {
                float4* o4 = (float4*)hout;
                o4[node * 4 + p * 2 + 0] = make_float4(v[0], v[1], v[2], v[3]);
                o4[node * 4 + p * 2 + 1] = make_float4(v[4], v[5], v[6], v[7]);
            }
        } else {
            // fused classify + log_softmax: partial logits over this half
            float lg[C_OUT];
            #pragma unroll
            for (int c = 0; c < C_OUT; c++) {
                float acc = 0.f;
                #pragma unroll
                for (int q = 0; q < 8; q++)
                    acc = fmaf(v[q], W2[c * H_DIM + p * 8 + q], acc);
                lg[c] = acc;
            }
            #pragma unroll
            for (int c = 0; c < C_OUT; c++)
                lg[c] += __shfl_xor_sync(pair_mask, lg[c], 1);
            if (p == 0 && store_ok) {
                #pragma unroll
                for (int c = 0; c < C_OUT; c++) lg[c] += b2[c];
                float mx = lg[0];
                #pragma unroll
                for (int c = 1; c < C_OUT; c++) mx = fmaxf(mx, lg[c]);
                float ssum = 0.f;
                #pragma unroll
                for (int c = 0; c < C_OUT; c++) ssum += __expf(lg[c] - mx);
                const float lse = mx + __logf(ssum);
                #pragma unroll
                for (int c = 0; c < C_OUT; c++) out[node * C_OUT + c] = lg[c] - lse;
            }
        }
    }
}

// ======================= launch ==============================================
extern "C" void kernel_launch(void* const* d_in, const int* in_sizes, int n_in,
                              void* d_out, int out_size)
{
    const float* x     = (const float*)d_in[0];
    const int*   ei    = (const int*)d_in[1];
    const float* W1    = (const float*)d_in[2];
    const float* b1    = (const float*)d_in[3];
    const float* beta2 = (const float*)d_in[4];
    const float* beta3 = (const float*)d_in[5];
    const float* beta4 = (const float*)d_in[6];
    const float* W2    = (const float*)d_in[7];
    const float* b2    = (const float*)d_in[8];
    float* out = (float*)d_out;

    const int N = in_sizes[0] / F_IN;
    const int E = in_sizes[1] / 2;
    const int NC = (N + CHUNK - 1) / CHUNK;

    float *hA, *hB;
    cudaGetSymbolAddress((void**)&hA, g_h0);
    cudaGetSymbolAddress((void**)&hB, g_h1);
    int* cntp;
    cudaGetSymbolAddress((void**)&cntp, g_counts);

    // lin1
    k_lin1<<<(N + 63) / 64, 256>>>(x, W1, b1, hA, N);

    // CSR build (real edges only; self-loops analytic in k_agnn)
    cudaMemsetAsync(cntp, 0, (size_t)N * sizeof(int));
    k_count<<<((E + 3) / 4 + 255) / 256, 256>>>(ei, E);
    k_csum<<<NC, 256>>>(N);
    k_scan<<<1, 256>>>(NC);
    k_cscan<<<NC, 512>>>(N);
    k_scatter<<<(E + 255) / 256, 256>>>(ei, E);

    // 4 AGNN layers (layer 0: beta fixed at 1.0; layer 3 fuses classify)
    const float* betas[4] = {nullptr, beta2, beta3, beta4};
    float* cur = hA; float* nxt = hB;
    for (int l = 0; l < 4; l++) {
        const int last = (l == 3);
        k_agnn<<<(N * 16 + 255) / 256, 256>>>(cur, nxt,
                                              betas[l], l > 0 ? 1 : 0, N,
                                              last, W2, b2, out);
        float* t = cur; cur = nxt; nxt = t;
    }
}

// round 17
// speedup vs baseline: 1.0663x; 1.0335x over previous
#include <cuda_runtime.h>

#define F_IN   512
#define H_DIM  16
#define C_OUT  7
#define NMAX   100000
#define EMAX   3200000
#define CHUNK  512
#define NCMAX  ((NMAX + CHUNK - 1) / CHUNK)

// -------- scratch (static device globals; no runtime allocation) --------
static __device__ float g_h0[NMAX * H_DIM];
static __device__ float g_h1[NMAX * H_DIM];
static __device__ int   g_counts[NMAX];
static __device__ int   g_cursor[NMAX];
static __device__ int   g_off[NMAX + 1];
static __device__ int   g_csr[EMAX];
static __device__ int   g_csums[NCMAX];

// packed f32x2 FMA: d = a*b + d (two fp32 lanes per instruction; PTX-only form)
__device__ __forceinline__ void fma2(unsigned long long& d,
                                     unsigned long long a, unsigned long long b)
{
    asm("fma.rn.f32x2 %0, %1, %2, %0;" : "+l"(d) : "l"(a), "l"(b));
}

__device__ __forceinline__ float unpack_sum(unsigned long long p)
{
    float lo = __uint_as_float((unsigned int)(p & 0xffffffffu));
    float hi = __uint_as_float((unsigned int)(p >> 32));
    return lo + hi;
}

// ======================= lin1: h = relu(x @ W1^T + b1) =======================
__global__ void k_lin1(const float* __restrict__ x, const float* __restrict__ W1,
                       const float* __restrict__ b1, float* __restrict__ h, int N)
{
    __shared__ float4 Ws[H_DIM * 129];
    const int tid = threadIdx.x;
    const float4* W14 = (const float4*)W1;
    for (int i = tid; i < H_DIM * 128; i += blockDim.x) {
        int k = i >> 7, j = i & 127;
        Ws[k * 129 + j] = W14[k * 128 + j];
    }
    __syncthreads();

    const int warp = tid >> 5, lane = tid & 31;
    const int k = lane & 15, slot = lane >> 4;
    const int row0 = (blockIdx.x * 8 + warp) * 8 + slot * 4;

    const int r0 = min(row0 + 0, N - 1);
    const int r1 = min(row0 + 1, N - 1);
    const int r2 = min(row0 + 2, N - 1);
    const int r3 = min(row0 + 3, N - 1);

    const float4* x4 = (const float4*)x;
    const float4* p0 = x4 + (size_t)r0 * 128;
    const float4* p1 = x4 + (size_t)r1 * 128;
    const float4* p2 = x4 + (size_t)r2 * 128;
    const float4* p3 = x4 + (size_t)r3 * 128;

    unsigned long long a0l = 0ull, a0h = 0ull, a1l = 0ull, a1h = 0ull;
    unsigned long long a2l = 0ull, a2h = 0ull, a3l = 0ull, a3h = 0ull;

    #pragma unroll 4
    for (int j = 0; j < 128; j++) {
        const float4 w = Ws[k * 129 + j];
        const ulonglong2 ww = *reinterpret_cast<const ulonglong2*>(&w);
        float4 v; ulonglong2 vv;
        v = p0[j]; vv = *reinterpret_cast<const ulonglong2*>(&v);
        fma2(a0l, vv.x, ww.x); fma2(a0h, vv.y, ww.y);
        v = p1[j]; vv = *reinterpret_cast<const ulonglong2*>(&v);
        fma2(a1l, vv.x, ww.x); fma2(a1h, vv.y, ww.y);
        v = p2[j]; vv = *reinterpret_cast<const ulonglong2*>(&v);
        fma2(a2l, vv.x, ww.x); fma2(a2h, vv.y, ww.y);
        v = p3[j]; vv = *reinterpret_cast<const ulonglong2*>(&v);
        fma2(a3l, vv.x, ww.x); fma2(a3h, vv.y, ww.y);
    }
    const float bk = b1[k];
    const float v0 = fmaxf(unpack_sum(a0l) + unpack_sum(a0h) + bk, 0.f);
    const float v1 = fmaxf(unpack_sum(a1l) + unpack_sum(a1h) + bk, 0.f);
    const float v2 = fmaxf(unpack_sum(a2l) + unpack_sum(a2h) + bk, 0.f);
    const float v3 = fmaxf(unpack_sum(a3l) + unpack_sum(a3h) + bk, 0.f);

    if (row0 + 0 < N) h[(row0 + 0) * H_DIM + k] = v0;
    if (row0 + 1 < N) h[(row0 + 1) * H_DIM + k] = v1;
    if (row0 + 2 < N) h[(row0 + 2) * H_DIM + k] = v2;
    if (row0 + 3 < N) h[(row0 + 3) * H_DIM + k] = v3;
}

// ======================= CSR build (dst-grouped, REAL edges only) ============
// Self-loops handled analytically in k_agnn (cos(i,i)=1 exactly): counts/csr
// cover only the E input edges; counts zeroed via cudaMemsetAsync.
__global__ void k_count(const int* __restrict__ ei, int E)
{
    int t = blockIdx.x * blockDim.x + threadIdx.x;
    int e = t * 4;
    if (e + 3 < E) {
        int4 d = *(const int4*)(ei + E + e);
        atomicAdd(&g_counts[d.x], 1);
        atomicAdd(&g_counts[d.y], 1);
        atomicAdd(&g_counts[d.z], 1);
        atomicAdd(&g_counts[d.w], 1);
    } else {
        for (int j = e; j < E; j++) atomicAdd(&g_counts[ei[E + j]], 1);
    }
}

__global__ void k_csum(int N)
{
    const int c = blockIdx.x;
    const int tid = threadIdx.x;           // 256 threads
    const int i = c * CHUNK + tid;
    int s = 0;
    if (i < N) s = g_counts[i];
    if (i + 256 < N && tid + 256 < CHUNK) s += g_counts[i + 256];
    #pragma unroll
    for (int o = 16; o > 0; o >>= 1) s += __shfl_xor_sync(0xffffffffu, s, o);
    __shared__ int ws[8];
    if ((tid & 31) == 0) ws[tid >> 5] = s;
    __syncthreads();
    if (tid < 8) {
        int v = ws[tid];
        #pragma unroll
        for (int o = 4; o > 0; o >>= 1) v += __shfl_xor_sync(0x000000ffu, v, o);
        if (tid == 0) g_csums[c] = v;
    }
}

__global__ void k_scan(int NC)
{
    const int tid = threadIdx.x;           // 256 threads
    const int lane = tid & 31, w = tid >> 5;
    int v = (tid < NC) ? g_csums[tid] : 0;
    int x = v;
    #pragma unroll
    for (int o = 1; o < 32; o <<= 1) {
        int t = __shfl_up_sync(0xffffffffu, x, o);
        if (lane >= o) x += t;
    }
    __shared__ int wsum[8];
    if (lane == 31) wsum[w] = x;
    __syncthreads();
    if (tid < 8) {
        int y = wsum[tid];
        #pragma unroll
        for (int o = 1; o < 8; o <<= 1) {
            int t = __shfl_up_sync(0x000000ffu, y, o);
            if (tid >= o) y += t;
        }
        wsum[tid] = y;
    }
    __syncthreads();
    const int incl = x + (w ? wsum[w - 1] : 0);
    if (tid < NC) g_csums[tid] = incl - v;   // exclusive
}

__global__ void k_cscan(int N)
{
    const int c = blockIdx.x;
    const int tid = threadIdx.x;           // 512 threads
    const int i = c * CHUNK + tid;
    const int lane = tid & 31, w = tid >> 5;   // 16 warps
    const int v = (i < N) ? g_counts[i] : 0;
    int x = v;
    #pragma unroll
    for (int o = 1; o < 32; o <<= 1) {
        int t = __shfl_up_sync(0xffffffffu, x, o);
        if (lane >= o) x += t;
    }
    __shared__ int wsum[16];
    if (lane == 31) wsum[w] = x;
    __syncthreads();
    if (tid < 16) {
        int y = wsum[tid];
        #pragma unroll
        for (int o = 1; o < 16; o <<= 1) {
            int t = __shfl_up_sync(0x0000ffffu, y, o);
            if (tid >= o) y += t;
        }
        wsum[tid] = y;
    }
    __syncthreads();
    const int excl = x - v + (w ? wsum[w - 1] : 0);
    const int off = g_csums[c] + excl;
    if (i < N) {
        g_off[i] = off;
        g_cursor[i] = off;
        if (i == N - 1) g_off[N] = off + v;
    }
}

// 4 edges per thread via int4 on both src and dst halves
__global__ void k_scatter(const int* __restrict__ ei, int E)
{
    int t = blockIdx.x * blockDim.x + threadIdx.x;
    int e = t * 4;
    if (e + 3 < E) {
        int4 sv = *(const int4*)(ei + e);
        int4 dv = *(const int4*)(ei + E + e);
        g_csr[atomicAdd(&g_cursor[dv.x], 1)] = sv.x;
        g_csr[atomicAdd(&g_cursor[dv.y], 1)] = sv.y;
        g_csr[atomicAdd(&g_cursor[dv.z], 1)] = sv.z;
        g_csr[atomicAdd(&g_cursor[dv.w], 1)] = sv.w;
    } else {
        for (int j = e; j < E; j++) {
            const int sv = ei[j];
            const int dv = ei[E + j];
            g_csr[atomicAdd(&g_cursor[dv], 1)] = sv;
        }
    }
}

// ======================= fused AGNN layer (R14 shape + analytic self) ========
// Pair-cooperative gather (confirmed optimum R14-R16): 8 lanes/node = 4 edge-
// slots x 2 lanes; each lane loads HALF the 64B src row; dot + src self-dot
// reduce with one pair shfl each; norms on the fly; combine = xor{2,4}.
// Self-loop analytic: w_self = exp(beta) with the register-resident dst row
// (no gather, CSR holds only real edges, degree-0 safe). No softmax max
// (|logit| <= |beta|). Last layer fuses classify + log_softmax.
__global__ void k_agnn(const float* __restrict__ hin, float* __restrict__ hout,
                       const float* __restrict__ betap, int use_beta, int N,
                       int last, const float* __restrict__ W2,
                       const float* __restrict__ b2, float* __restrict__ out)
{
    const int gid = blockIdx.x * blockDim.x + threadIdx.x;
    int node = gid >> 3;
    const int o8   = gid & 7;        // position within octet
    const int slot = o8 >> 1;        // 0..3  edge slot
    const int p    = o8 & 1;         // 0..1  row half
    const unsigned pair_mask = 3u << ((threadIdx.x & 31) & ~1);
    const bool store_ok = (node < N);
    if (node >= N) node = N - 1;     // clamp: keep lanes alive for shuffles

    const float beta = use_beta ? betap[0] : 1.0f;
    const float4* __restrict__ h4 = (const float4*)hin;

    // this lane's half of the dst row + on-the-fly dst inverse norm
    float hd[8];
    {
        float4 a = h4[node * 4 + p * 2 + 0];
        float4 b = h4[node * 4 + p * 2 + 1];
        hd[0] = a.x; hd[1] = a.y; hd[2] = a.z; hd[3] = a.w;
        hd[4] = b.x; hd[5] = b.y; hd[6] = b.z; hd[7] = b.w;
    }
    float sd = 0.f;
    #pragma unroll
    for (int q = 0; q < 8; q++) sd = fmaf(hd[q], hd[q], sd);
    sd += __shfl_xor_sync(pair_mask, sd, 1);
    const float cd = beta * rsqrtf(fmaxf(sd, 1e-24f));

    const int beg = g_off[node], end = g_off[node + 1];

    float s = 0.f;
    float n[8];
    #pragma unroll
    for (int q = 0; q < 8; q++) n[q] = 0.f;

    int i = beg + slot;
    if (i < end) {
        int src = g_csr[i];
        while (i < end) {
            const int csrc = src;
            const float4 a0 = h4[csrc * 4 + p * 2 + 0];
            const float4 a1 = h4[csrc * 4 + p * 2 + 1];
            i += 4;
            if (i < end) src = g_csr[i];   // prefetch next edge's index
            float hs[8];
            hs[0] = a0.x; hs[1] = a0.y; hs[2] = a0.z; hs[3] = a0.w;
            hs[4] = a1.x; hs[5] = a1.y; hs[6] = a1.z; hs[7] = a1.w;
            float pd = 0.f, ps = 0.f;
            #pragma unroll
            for (int q = 0; q < 8; q++) {
                pd = fmaf(hd[q], hs[q], pd);
                ps = fmaf(hs[q], hs[q], ps);
            }
            pd += __shfl_xor_sync(pair_mask, pd, 1);
            ps += __shfl_xor_sync(pair_mask, ps, 1);
            const float w = __expf(cd * rsqrtf(fmaxf(ps, 1e-24f)) * pd);
            s += w;
            #pragma unroll
            for (int q = 0; q < 8; q++) n[q] = fmaf(w, hs[q], n[q]);
        }
    }

    // combine across the 4 slots (preserves half p); s becomes the full sum
    #pragma unroll
    for (int o = 2; o <= 4; o <<= 1) {
        s += __shfl_xor_sync(0xffffffffu, s, o);
        #pragma unroll
        for (int q = 0; q < 8; q++)
            n[q] += __shfl_xor_sync(0xffffffffu, n[q], o);
    }

    if (slot == 0) {   // lanes o8==0 (half 0) and o8==1 (half 1)
        // analytic self-loop: cos(i,i) = 1 -> weight exp(beta); row in regs
        const float wself = __expf(beta);
        s += wself;
        #pragma unroll
        for (int q = 0; q < 8; q++) n[q] = fmaf(wself, hd[q], n[q]);

        const float is = 1.0f / s;
        float v[8];
        #pragma unroll
        for (int q = 0; q < 8; q++) v[q] = n[q] * is;

        if (!last) {
            if (store_ok) {
                float4* o4 = (float4*)hout;
                o4[node * 4 + p * 2 + 0] = make_float4(v[0], v[1], v[2], v[3]);
                o4[node * 4 + p * 2 + 1] = make_float4(v[4], v[5], v[6], v[7]);
            }
        } else {
            // fused classify + log_softmax: partial logits over this half
            float lg[C_OUT];
            #pragma unroll
            for (int c = 0; c < C_OUT; c++) {
                float acc = 0.f;
                #pragma unroll
                for (int q = 0; q < 8; q++)
                    acc = fmaf(v[q], W2[c * H_DIM + p * 8 + q], acc);
                lg[c] = acc;
            }
            #pragma unroll
            for (int c = 0; c < C_OUT; c++)
                lg[c] += __shfl_xor_sync(pair_mask, lg[c], 1);
            if (p == 0 && store_ok) {
                #pragma unroll
                for (int c = 0; c < C_OUT; c++) lg[c] += b2[c];
                float mx = lg[0];
                #pragma unroll
                for (int c = 1; c < C_OUT; c++) mx = fmaxf(mx, lg[c]);
                float ssum = 0.f;
                #pragma unroll
                for (int c = 0; c < C_OUT; c++) ssum += __expf(lg[c] - mx);
                const float lse = mx + __logf(ssum);
                #pragma unroll
                for (int c = 0; c < C_OUT; c++) out[node * C_OUT + c] = lg[c] - lse;
            }
        }
    }
}

// ======================= launch ==============================================
extern "C" void kernel_launch(void* const* d_in, const int* in_sizes, int n_in,
                              void* d_out, int out_size)
{
    const float* x     = (const float*)d_in[0];
    const int*   ei    = (const int*)d_in[1];
    const float* W1    = (const float*)d_in[2];
    const float* b1    = (const float*)d_in[3];
    const float* beta2 = (const float*)d_in[4];
    const float* beta3 = (const float*)d_in[5];
    const float* beta4 = (const float*)d_in[6];
    const float* W2    = (const float*)d_in[7];
    const float* b2    = (const float*)d_in[8];
    float* out = (float*)d_out;

    const int N = in_sizes[0] / F_IN;
    const int E = in_sizes[1] / 2;
    const int NC = (N + CHUNK - 1) / CHUNK;

    float *hA, *hB;
    cudaGetSymbolAddress((void**)&hA, g_h0);
    cudaGetSymbolAddress((void**)&hB, g_h1);
    int* cntp;
    cudaGetSymbolAddress((void**)&cntp, g_counts);

    // lin1
    k_lin1<<<(N + 63) / 64, 256>>>(x, W1, b1, hA, N);

    // CSR build (real edges only; self-loops analytic in k_agnn)
    cudaMemsetAsync(cntp, 0, (size_t)N * sizeof(int));
    k_count<<<((E + 3) / 4 + 255) / 256, 256>>>(ei, E);
    k_csum<<<NC, 256>>>(N);
    k_scan<<<1, 256>>>(NC);
    k_cscan<<<NC, 512>>>(N);
    k_scatter<<<((E + 3) / 4 + 255) / 256, 256>>>(ei, E);

    // 4 AGNN layers (layer 0: beta fixed at 1.0; layer 3 fuses classify)
    const float* betas[4] = {nullptr, beta2, beta3, beta4};
    float* cur = hA; float* nxt = hB;
    for (int l = 0; l < 4; l++) {
        const int last = (l == 3);
        k_agnn<<<(N * 8 + 255) / 256, 256>>>(cur, nxt,
                                             betas[l], l > 0 ? 1 : 0, N,
                                             last, W2, b2, out);
        float* t = cur; cur = nxt; nxt = t;
    }
}